// round 16
// baseline (speedup 1.0000x reference)
#include <cuda_runtime.h>
#include <cuda_bf16.h>
#include <math.h>
#include <stdint.h>

#define LAYERS 4
#define BB 4
#define SS 2048
#define DD 1024
#define HH 2048
#define MTOK (BB*SS)      /* 8192 tokens */
#define EPSLN 1e-5f

#define CHUNKS 16
#define CLOG 4
#define CLEN (SS/CHUNKS)  /* 128 */

// arch-feature gate: tcgen05 only exists on the sm_103a/sm_100a ("a") targets.
#if defined(__CUDA_ARCH_FEAT_SM103_ALL) || defined(__CUDA_ARCH_FEAT_SM100_ALL)
#define USE_TC5 1
#else
#define USE_TC5 0
#endif

// ---- GEMM tiling ----
// CTA tile: 256(M) x 256(N). Two M=128 MMA accumulators in TMEM (cols 0-255, 256-511).
// K pipelined in FOUR 16-element stages = 32B column-quarters of the 128B-row SW128
// tiles (slot = stage & 3). Loads run 3 stages ahead of the tensor pipe.
// PERSISTENT: each CTA processes `mtiles` M-tiles (bm, bm + gridDim.y*TM, ...) as one
// continuous stage stream -- tile t+1's first loads overlap tile t's epilogue.
#define TM 256
#define TN 256
#define SM_A_HI 0          /* 256 rows x 128B */
#define SM_A_LO 32768
#define SM_B_HI 65536
#define SM_B_LO 98304
#define TILE_BYTES 131072
#define SMEM_DYN (1024 + 1024 + TILE_BYTES)

// ------------------------- scratch -------------------------------------------
__device__ __align__(256) float g_b0[(size_t)MTOK*HH];
__device__ __align__(256) float g_b2[(size_t)MTOK*HH];
__device__ __align__(256) float g_b3[(size_t)MTOK*HH];
__device__ __align__(256) float g_b4[(size_t)MTOK*HH];
__device__ __align__(256) __nv_bfloat16 g_cvth[(size_t)MTOK*HH];   // activation split
__device__ __align__(256) __nv_bfloat16 g_cvtl[(size_t)MTOK*HH];
__device__ __align__(256) __nv_bfloat16 g_cvtxh[(size_t)MTOK*DD];  // x split
__device__ __align__(256) __nv_bfloat16 g_cvtxl[(size_t)MTOK*DD];
__device__ __align__(256) __nv_bfloat16 g_wp1h[(size_t)LAYERS*HH*DD];
__device__ __align__(256) __nv_bfloat16 g_wp1l[(size_t)LAYERS*HH*DD];
__device__ __align__(256) __nv_bfloat16 g_wp2h[(size_t)LAYERS*HH*DD];
__device__ __align__(256) __nv_bfloat16 g_wp2l[(size_t)LAYERS*HH*DD];
__device__ __align__(256) __nv_bfloat16 g_wzh[(size_t)LAYERS*HH*HH];
__device__ __align__(256) __nv_bfloat16 g_wzl[(size_t)LAYERS*HH*HH];
__device__ __align__(256) __nv_bfloat16 g_whh[(size_t)LAYERS*HH*HH];
__device__ __align__(256) __nv_bfloat16 g_whl[(size_t)LAYERS*HH*HH];
__device__ __align__(256) __nv_bfloat16 g_wdh[(size_t)LAYERS*DD*HH];
__device__ __align__(256) __nv_bfloat16 g_wdl[(size_t)LAYERS*DD*HH];
__device__ __align__(256) __nv_bfloat16 g_wch[(size_t)LAYERS*3*HH*HH];
__device__ __align__(256) __nv_bfloat16 g_wcl[(size_t)LAYERS*3*HH*HH];
__device__ float g_rend[BB*CHUNKS*HH];
__device__ float g_asum[BB*CHUNKS*HH];
__device__ float g_lhin[BB*CHUNKS*HH];

// ------------------------- helpers --------------------------------------------
__device__ __forceinline__ uint32_t smem_u32(const void* p) {
    uint32_t a;
    asm("{ .reg .u64 t; cvta.to.shared.u64 t, %1; cvt.u32.u64 %0, t; }" : "=r"(a) : "l"(p));
    return a;
}
#define SW128(b) ((b) ^ (((b) >> 3) & 0x70))

__device__ __forceinline__ void cpasync16(uint32_t dst, const void* src, int srcsize) {
    asm volatile("cp.async.cg.shared.global [%0], [%1], 16, %2;\n"
                 :: "r"(dst), "l"(src), "r"(srcsize));
}

__device__ __forceinline__ void split_store(float v, __nv_bfloat16* hi, __nv_bfloat16* lo) {
    __nv_bfloat16 h = __float2bfloat16(v);
    *hi = h;
    *lo = __float2bfloat16(v - __bfloat162float(h));
}
__device__ __forceinline__ void split4(float4 v, uint2& h, uint2& l) {
    __nv_bfloat16 hx = __float2bfloat16(v.x), hy = __float2bfloat16(v.y);
    __nv_bfloat16 hz = __float2bfloat16(v.z), hw = __float2bfloat16(v.w);
    __nv_bfloat16 lx = __float2bfloat16(v.x - __bfloat162float(hx));
    __nv_bfloat16 ly = __float2bfloat16(v.y - __bfloat162float(hy));
    __nv_bfloat16 lz = __float2bfloat16(v.z - __bfloat162float(hz));
    __nv_bfloat16 lw = __float2bfloat16(v.w - __bfloat162float(hw));
    h.x = (uint32_t)__bfloat16_as_ushort(hx) | ((uint32_t)__bfloat16_as_ushort(hy) << 16);
    h.y = (uint32_t)__bfloat16_as_ushort(hz) | ((uint32_t)__bfloat16_as_ushort(hw) << 16);
    l.x = (uint32_t)__bfloat16_as_ushort(lx) | ((uint32_t)__bfloat16_as_ushort(ly) << 16);
    l.y = (uint32_t)__bfloat16_as_ushort(lz) | ((uint32_t)__bfloat16_as_ushort(lw) << 16);
}

#if USE_TC5
__device__ __forceinline__ uint32_t elect_one_pred() {
    uint32_t pred;
    asm volatile("{\n\t.reg .pred p;\n\telect.sync _|p, 0xFFFFFFFF;\n\t"
                 "selp.b32 %0, 1, 0, p;\n\t}" : "=r"(pred));
    return pred;
}

static constexpr uint64_t SMEM_DESC_BASE_SW128 =
    (uint64_t(2) << 61) | (uint64_t(1) << 46) | (uint64_t(64) << 32) | (uint64_t(1) << 16);
#define MAKE_SMEM_DESC(base_addr) \
    (SMEM_DESC_BASE_SW128 | ((uint64_t)((base_addr) >> 4) & 0x3FFF))

#define TCGEN05_ALLOC(smem_result_addr, nCols) \
    asm volatile("tcgen05.alloc.cta_group::1.sync.aligned.shared::cta.b32 [%0], %1;" \
        :: "r"((uint32_t)(smem_result_addr)), "r"((uint32_t)(nCols)) : "memory")
#define TCGEN05_DEALLOC(tmem_addr, nCols) \
    asm volatile("tcgen05.dealloc.cta_group::1.sync.aligned.b32 %0, %1;" \
        :: "r"(tmem_addr), "r"((uint32_t)(nCols)))
#define TCGEN05_RELINQUISH() \
    asm volatile("tcgen05.relinquish_alloc_permit.cta_group::1.sync.aligned;")
#define TCGEN05_COMMIT(mbar) \
    asm volatile("tcgen05.commit.cta_group::1.mbarrier::arrive::one.shared::cluster.b64 [%0];" \
        :: "r"((uint32_t)(mbar)) : "memory")
#define TCGEN05_FENCE_AFTER() \
    asm volatile("tcgen05.fence::after_thread_sync;" ::: "memory")
#define TCGEN05_FENCE_BEFORE() \
    asm volatile("tcgen05.fence::before_thread_sync;" ::: "memory")
#define TCGEN05_WAIT_LD() \
    asm volatile("tcgen05.wait::ld.sync.aligned;" ::: "memory")
#define MBARRIER_INIT(mbar, cnt) \
    asm volatile("mbarrier.init.shared.b64 [%0], %1;" \
        :: "r"((uint32_t)(mbar)), "r"((uint32_t)(cnt)) : "memory")
#define MBARRIER_INVAL(mbar) \
    asm volatile("mbarrier.inval.shared.b64 [%0];" :: "r"((uint32_t)(mbar)) : "memory")

#define MBARRIER_WAIT_PARITY(mbar_smem_addr, phase_parity) do { \
    uint32_t _mbar = (uint32_t)(mbar_smem_addr); \
    uint32_t _parity = (uint32_t)(phase_parity); \
    uint32_t _done; \
    asm volatile("{\n\t.reg .pred p;\n\t" \
        "mbarrier.try_wait.parity.acquire.cta.shared::cta.b64 p, [%1], %2;\n\t" \
        "selp.b32 %0, 1, 0, p;\n\t}" : "=r"(_done) : "r"(_mbar), "r"(_parity) : "memory"); \
    if (!_done) { \
        asm volatile("{\n\t.reg .pred P1;\n\t" \
            "WAIT_LOOP_%=:\n\t" \
            "mbarrier.try_wait.parity.acquire.cta.shared::cta.b64 P1, [%0], %1, 0x989680;\n\t" \
            "@P1 bra.uni WAIT_DONE_%=;\n\t" \
            "bra.uni WAIT_LOOP_%=;\n\t" \
            "WAIT_DONE_%=:\n\t}" :: "r"(_mbar), "r"(_parity) : "memory"); \
    } \
} while(0)

#define TCGEN05_LD_X32(r, tmem_addr) \
    asm volatile("tcgen05.ld.sync.aligned.32x32b.x32.b32 " \
        "{%0, %1, %2, %3, %4, %5, %6, %7, %8, %9, %10, %11, %12, %13, %14, %15, " \
        "%16, %17, %18, %19, %20, %21, %22, %23, %24, %25, %26, %27, %28, %29, %30, %31}, [%32];" \
        : "=r"((r)[0]),  "=r"((r)[1]),  "=r"((r)[2]),  "=r"((r)[3]), \
          "=r"((r)[4]),  "=r"((r)[5]),  "=r"((r)[6]),  "=r"((r)[7]), \
          "=r"((r)[8]),  "=r"((r)[9]),  "=r"((r)[10]), "=r"((r)[11]), \
          "=r"((r)[12]), "=r"((r)[13]), "=r"((r)[14]), "=r"((r)[15]), \
          "=r"((r)[16]), "=r"((r)[17]), "=r"((r)[18]), "=r"((r)[19]), \
          "=r"((r)[20]), "=r"((r)[21]), "=r"((r)[22]), "=r"((r)[23]), \
          "=r"((r)[24]), "=r"((r)[25]), "=r"((r)[26]), "=r"((r)[27]), \
          "=r"((r)[28]), "=r"((r)[29]), "=r"((r)[30]), "=r"((r)[31]) \
        : "r"(tmem_addr))

__device__ __forceinline__ void mma_f16_ss(uint32_t d, uint64_t ad, uint64_t bd,
                                           uint32_t idesc, uint32_t en) {
    asm volatile("{\n\t.reg .pred p;\n\tsetp.ne.u32 p, %4, 0;\n\t"
        "tcgen05.mma.cta_group::1.kind::f16 [%0], %1, %2, %3, {%5, %5, %5, %5}, p;\n\t}"
        :: "r"(d), "l"(ad), "l"(bd), "r"(idesc), "r"(en), "r"(0u) : "memory");
}
#endif

// ------------------------------- GEMM -----------------------------------------
// C[M=8192, N] (+)= sum_taps sum_k A'[m,k]*B_tap[n,k] + bias[n]
// A' rows shifted by (tap-1) within each batch (zero pad) when taps==3.
// hi/lo split bf16: acc += Ah*Bh + Ah*Bl + Al*Bh (fp32 accumulate in TMEM).
// Stage c = 16 K-elements in 32B column-quarter (slot c&3) of the 128B-row tiles.
__device__ __forceinline__ void load_stage(
    int c, int kpt, int taps, int K,
    const __nv_bfloat16* __restrict__ Ahi, const __nv_bfloat16* __restrict__ Alo,
    const __nv_bfloat16* __restrict__ Bhi, const __nv_bfloat16* __restrict__ Blo,
    size_t tapStrideB, int bm, int bn, uint32_t tb)
{
    int tap = 0, kc = c;
    if (taps == 3) { tap = c / kpt; kc = c - tap * kpt; }
    const int shift = (taps == 3) ? (tap - 1) : 0;
    const int kbase = kc << 4;                 // 16 K per stage
    const uint32_t colb = (uint32_t)(c & 3) * 32;
    const int tid = threadIdx.x;

    // A: 256 rows x 2 16B-units (this quarter)
#pragma unroll
    for (int it = 0; it < 2; ++it) {
        const int u = tid + it * 256;
        const int r = u >> 1, c2 = u & 1;
        const int m = bm + r;
        const int t = m & (SS - 1);
        const bool ok = ((unsigned)(t + shift)) < (unsigned)SS;
        const int srcsz = ok ? 16 : 0;
        const size_t goff = (size_t)(ok ? (m + shift) : m) * K + kbase + c2 * 8;
        const uint32_t so = SW128((uint32_t)(r * 128 + colb + c2 * 16));
        cpasync16(tb + SM_A_HI + so, Ahi + goff, srcsz);
        cpasync16(tb + SM_A_LO + so, Alo + goff, srcsz);
    }
    // B: 256 rows x 2 units
    const __nv_bfloat16* Bh = Bhi + (size_t)tap * tapStrideB;
    const __nv_bfloat16* Bl = Blo + (size_t)tap * tapStrideB;
#pragma unroll
    for (int it = 0; it < 2; ++it) {
        const int u = tid + it * 256;
        const int r = u >> 1, c2 = u & 1;
        const size_t goff = (size_t)(bn + r) * K + kbase + c2 * 8;
        const uint32_t so = SW128((uint32_t)(r * 128 + colb + c2 * 16));
        cpasync16(tb + SM_B_HI + so, Bh + goff, 16);
        cpasync16(tb + SM_B_LO + so, Bl + goff, 16);
    }
}

__global__ __launch_bounds__(256, 1)
void gemm_ts(const __nv_bfloat16* __restrict__ Ahi, const __nv_bfloat16* __restrict__ Alo,
             const __nv_bfloat16* __restrict__ Bhi, const __nv_bfloat16* __restrict__ Blo,
             const float* __restrict__ bias, float* __restrict__ C,
             int N, int K, int taps, size_t tapStrideB, int accum,
             __nv_bfloat16* __restrict__ XsHi, __nv_bfloat16* __restrict__ XsLo,
             int mtiles)
{
    extern __shared__ char dsm[];
    const uint32_t raw = smem_u32(dsm);
    const uint32_t sb0 = (raw + 1023) & ~1023u;     // header (tmem ptr, mbar)
    const uint32_t tb  = sb0 + 1024;                // tiles, 1KB aligned

    const int tid = threadIdx.x;
    const int wid = tid >> 5;
    const int lane = tid & 31;
    const int bn = blockIdx.x * TN;
    const int kpt = K >> 4;                          // 16-K stages per tap
    const int nch = taps * kpt;                      // stages per M-tile (mult of 4)
    const int S = mtiles * nch;                      // global stage stream length

#if USE_TC5
    const uint32_t mb0 = sb0 + 8;
    if (wid == 0) { TCGEN05_ALLOC(sb0, 512); TCGEN05_RELINQUISH(); }
    if (tid == 0) { MBARRIER_INIT(mb0, 1); }
    __syncthreads();
    uint32_t tmem;
    asm volatile("ld.shared.b32 %0, [%1];" : "=r"(tmem) : "r"(sb0));

    // per-MMA: M=128, N=256, K=16, bf16 in, fp32 out
    const uint32_t idesc = (1u << 4) | (1u << 7) | (1u << 10)
                         | ((TN / 8) << 17) | ((128 / 16) << 24);

    const uint64_t dAh0 = MAKE_SMEM_DESC(tb + SM_A_HI);
    const uint64_t dAh1 = MAKE_SMEM_DESC(tb + SM_A_HI + 16384);
    const uint64_t dAl0 = MAKE_SMEM_DESC(tb + SM_A_LO);
    const uint64_t dAl1 = MAKE_SMEM_DESC(tb + SM_A_LO + 16384);
    const uint64_t dBh  = MAKE_SMEM_DESC(tb + SM_B_HI);
    const uint64_t dBl  = MAKE_SMEM_DESC(tb + SM_B_LO);

    // prologue: fill 3 of the 4 slots with tile-0 stages (nch >= 64 > 3)
    {
        const int bm0 = blockIdx.y * TM;
        load_stage(0, kpt, taps, K, Ahi, Alo, Bhi, Blo, tapStrideB, bm0, bn, tb);
        asm volatile("cp.async.commit_group;" ::: "memory");
        load_stage(1, kpt, taps, K, Ahi, Alo, Bhi, Blo, tapStrideB, bm0, bn, tb);
        asm volatile("cp.async.commit_group;" ::: "memory");
        load_stage(2, kpt, taps, K, Ahi, Alo, Bhi, Blo, tapStrideB, bm0, bn, tb);
        asm volatile("cp.async.commit_group;" ::: "memory");
    }

    int ph = 0;
    for (int t = 0; t < mtiles; ++t) {
        const int bm = (blockIdx.y + t * gridDim.y) * TM;
        for (int c = 0; c < nch; ++c) {
            const int sg = t * nch + c;              // global stage
            const int rem = S - 1 - sg;
            if (rem >= 2)      asm volatile("cp.async.wait_group 2;" ::: "memory");
            else if (rem == 1) asm volatile("cp.async.wait_group 1;" ::: "memory");
            else               asm volatile("cp.async.wait_group 0;" ::: "memory");
            __syncthreads();

            if (wid == 0) {
                if (elect_one_pred()) {
                    asm volatile("fence.proxy.async.shared::cta;" ::: "memory");
                    const uint32_t cofs = (uint32_t)(c & 3) * 2;   // 32B col offset, 16B units
                    const uint32_t en0 = (c == 0) ? 0u : 1u;       // zero acc per tile
                    mma_f16_ss(tmem,       dAh0 + cofs, dBh + cofs, idesc, en0);
                    mma_f16_ss(tmem,       dAh0 + cofs, dBl + cofs, idesc, 1u);
                    mma_f16_ss(tmem,       dAl0 + cofs, dBh + cofs, idesc, 1u);
                    mma_f16_ss(tmem + 256, dAh1 + cofs, dBh + cofs, idesc, en0);
                    mma_f16_ss(tmem + 256, dAh1 + cofs, dBl + cofs, idesc, 1u);
                    mma_f16_ss(tmem + 256, dAl1 + cofs, dBh + cofs, idesc, 1u);
                    TCGEN05_COMMIT(mb0);
                }
            }
            // wait for MMA(sg-1 within tile): frees slot (sg+3)&3 for refill
            if (c >= 1) { MBARRIER_WAIT_PARITY(mb0, ph); ph ^= 1; }
            const int s3 = sg + 3;
            if (s3 < S) {
                const int tt = (s3 >= nch * (t + 1)) ? (t + 1) : t;
                const int cc = s3 - tt * nch;
                const int bml = (blockIdx.y + tt * gridDim.y) * TM;
                load_stage(cc, kpt, taps, K, Ahi, Alo, Bhi, Blo,
                           tapStrideB, bml, bn, tb);
                asm volatile("cp.async.commit_group;" ::: "memory");
            }
        }
        // final wait for this tile's last MMA
        MBARRIER_WAIT_PARITY(mb0, ph); ph ^= 1;
        TCGEN05_FENCE_AFTER();

        // epilogue for tile t: 8 warps; 0-3 -> M-half 0 (cols 0-255), 4-7 -> half 1
        {
            const int h = wid >> 2;
            const int row = bm + h * 128 + (wid & 3) * 32 + lane;
            float* crow = C + (size_t)row * N + bn;
            const uint32_t tbase = tmem + (uint32_t)h * 256;
#pragma unroll 1
            for (int g = 0; g < 8; ++g) {
                uint32_t r[32];
                TCGEN05_LD_X32(r, tbase + g * 32);
                TCGEN05_WAIT_LD();
                const int cb = g * 32;
#pragma unroll
                for (int j = 0; j < 8; ++j) {
                    float4 o;
                    o.x = __uint_as_float(r[j * 4 + 0]);
                    o.y = __uint_as_float(r[j * 4 + 1]);
                    o.z = __uint_as_float(r[j * 4 + 2]);
                    o.w = __uint_as_float(r[j * 4 + 3]);
                    if (bias) {
                        float4 bi = *(const float4*)(bias + bn + cb + j * 4);
                        o.x += bi.x; o.y += bi.y; o.z += bi.z; o.w += bi.w;
                    }
                    if (accum) {
                        float4 p = *(const float4*)(crow + cb + j * 4);
                        o.x += p.x; o.y += p.y; o.z += p.z; o.w += p.w;
                    }
                    *(float4*)(crow + cb + j * 4) = o;
                    if (XsHi) {
                        uint2 hh, ll;
                        split4(o, hh, ll);
                        const size_t xo = (size_t)row * N + bn + cb + j * 4;
                        *(uint2*)(XsHi + xo) = hh;
                        *(uint2*)(XsLo + xo) = ll;
                    }
                }
            }
            TCGEN05_FENCE_BEFORE();
        }
        __syncthreads();   // all LDTMs done before next tile's first MMA (en=0 write)
    }
    if (tid == 0) { MBARRIER_INVAL(mb0); }
    if (wid == 0) { TCGEN05_DEALLOC(tmem, 512); }
#else
    // Correct SIMT fallback for non-'a' compile targets (never runs on GB300).
    (void)tb; (void)wid; (void)lane;
    for (int t = 0; t < mtiles; ++t) {
        const int bm = (blockIdx.y + t * gridDim.y) * TM;
        for (int idx = tid; idx < TM * TN; idx += 256) {
            const int mi = idx >> 8;          // 0..255 (row within tile)
            const int ni = idx & 255;
            const int row = bm + mi;
            const int col = bn + ni;
            float acc = bias ? bias[col] : 0.f;
            for (int tap = 0; tap < taps; ++tap) {
                const int shift = (taps == 3) ? (tap - 1) : 0;
                const int tt2 = row & (SS - 1);
                if (((unsigned)(tt2 + shift)) >= (unsigned)SS) continue;
                const __nv_bfloat16* ar = Ahi + (size_t)(row + shift) * K;
                const __nv_bfloat16* al = Alo + (size_t)(row + shift) * K;
                const __nv_bfloat16* br = Bhi + (size_t)tap * tapStrideB + (size_t)col * K;
                const __nv_bfloat16* bl = Blo + (size_t)tap * tapStrideB + (size_t)col * K;
                for (int k = 0; k < K; ++k) {
                    float a = __bfloat162float(ar[k]), a2 = __bfloat162float(al[k]);
                    float b = __bfloat162float(br[k]), b2 = __bfloat162float(bl[k]);
                    acc += a * b + a * b2 + a2 * b;
                }
            }
            float* p = C + (size_t)row * N + col;
            float v = acc + (accum ? *p : 0.f);
            *p = v;
            if (XsHi) split_store(v, XsHi + (size_t)row * N + col, XsLo + (size_t)row * N + col);
        }
    }
#endif
}

// ------------------------- conversions ----------------------------------------
__global__ void cvt_split(const float* __restrict__ in, __nv_bfloat16* __restrict__ hi,
                          __nv_bfloat16* __restrict__ lo, int n4)
{
    const int i = blockIdx.x * 256 + threadIdx.x;
    if (i < n4) {
        float4 v = ((const float4*)in)[i];
        uint2 h, l;
        split4(v, h, l);
        ((uint2*)hi)[i] = h;
        ((uint2*)lo)[i] = l;
    }
}

// convW [L][O=H][I=H][3] -> [L][tap][O][I] split; one thread per (l,o,i) triple
__global__ void cvt_convw(const float* __restrict__ w, __nv_bfloat16* __restrict__ hi,
                          __nv_bfloat16* __restrict__ lo)
{
    const size_t idx = (size_t)blockIdx.x * 256 + threadIdx.x;  // over L*H*H
    const size_t total = (size_t)LAYERS * HH * HH;
    if (idx < total) {
        const int i = (int)(idx & (HH - 1));
        size_t r = idx >> 11;
        const int o = (int)(r & (HH - 1));
        const int l = (int)(r >> 11);
        const float* p = w + idx * 3;
#pragma unroll
        for (int tap = 0; tap < 3; ++tap) {
            const size_t dst = (((size_t)l * 3 + tap) * HH + o) * HH + i;
            split_store(p[tap], hi + dst, lo + dst);
        }
    }
}

// ------------------------------ LayerNorm family ------------------------------
#define LN_PROLOG() \
    __shared__ float red[8]; \
    __shared__ float s_mean, s_rstd; \
    const int row = blockIdx.x; \
    const float4* ip = (const float4*)(in + (size_t)row * HH); \
    float4 v0 = ip[threadIdx.x]; \
    float4 v1 = ip[threadIdx.x + 256]; \
    float s = v0.x+v0.y+v0.z+v0.w + v1.x+v1.y+v1.z+v1.w; \
    _Pragma("unroll") \
    for (int o = 16; o; o >>= 1) s += __shfl_xor_sync(0xffffffffu, s, o); \
    const int wid = threadIdx.x >> 5, lane = threadIdx.x & 31; \
    if (lane == 0) red[wid] = s; \
    __syncthreads(); \
    if (threadIdx.x == 0) { \
        float tt = 0.f; \
        _Pragma("unroll") \
        for (int i = 0; i < 8; i++) tt += red[i]; \
        s_mean = tt * (1.0f / HH); \
    } \
    __syncthreads(); \
    const float mean = s_mean; \
    float d, ss = 0.f; \
    d=v0.x-mean; ss+=d*d; d=v0.y-mean; ss+=d*d; d=v0.z-mean; ss+=d*d; d=v0.w-mean; ss+=d*d; \
    d=v1.x-mean; ss+=d*d; d=v1.y-mean; ss+=d*d; d=v1.z-mean; ss+=d*d; d=v1.w-mean; ss+=d*d; \
    _Pragma("unroll") \
    for (int o = 16; o; o >>= 1) ss += __shfl_xor_sync(0xffffffffu, ss, o); \
    if (lane == 0) red[wid] = ss; \
    __syncthreads(); \
    if (threadIdx.x == 0) { \
        float tt = 0.f; \
        _Pragma("unroll") \
        for (int i = 0; i < 8; i++) tt += red[i]; \
        s_rstd = rsqrtf(tt * (1.0f / HH) + EPSLN); \
    } \
    __syncthreads(); \
    const float rstd = s_rstd; \
    float4 g0 = ((const float4*)g)[threadIdx.x]; \
    float4 g1 = ((const float4*)g)[threadIdx.x + 256]; \
    float4 b0 = ((const float4*)b)[threadIdx.x]; \
    float4 b1 = ((const float4*)b)[threadIdx.x + 256]; \
    float4 o0, o1; \
    o0.x=(v0.x-mean)*rstd*g0.x+b0.x; o0.y=(v0.y-mean)*rstd*g0.y+b0.y; \
    o0.z=(v0.z-mean)*rstd*g0.z+b0.z; o0.w=(v0.w-mean)*rstd*g0.w+b0.w; \
    o1.x=(v1.x-mean)*rstd*g1.x+b1.x; o1.y=(v1.y-mean)*rstd*g1.y+b1.y; \
    o1.z=(v1.z-mean)*rstd*g1.z+b1.z; o1.w=(v1.w-mean)*rstd*g1.w+b1.w;

__device__ __forceinline__ float4 silu4(float4 v) {
    v.x = v.x / (1.f + expf(-v.x)); v.y = v.y / (1.f + expf(-v.y));
    v.z = v.z / (1.f + expf(-v.z)); v.w = v.w / (1.f + expf(-v.w));
    return v;
}

// LN -> split bf16 out (optionally SiLU)  [LN0, LN1]
template<int DO_SILU>
__global__ void ln_split(const float* __restrict__ in,
                         __nv_bfloat16* __restrict__ oh, __nv_bfloat16* __restrict__ ol,
                         const float* __restrict__ g, const float* __restrict__ b)
{
    LN_PROLOG();
    if (DO_SILU) { o0 = silu4(o0); o1 = silu4(o1); }
    uint2 h0, l0, h1, l1;
    split4(o0, h0, l0);
    split4(o1, h1, l1);
    uint2* hp = (uint2*)(oh + (size_t)row * HH);
    uint2* lp = (uint2*)(ol + (size_t)row * HH);
    hp[threadIdx.x] = h0; hp[threadIdx.x + 256] = h1;
    lp[threadIdx.x] = l0; lp[threadIdx.x + 256] = l1;
}

// Double-LN gating: split( LN(in;g,b) * SiLU(LN(p2;g2,b2)) ).
__global__ void ln2_mul_split(const float* __restrict__ in, const float* __restrict__ p2,
                              __nv_bfloat16* __restrict__ oh, __nv_bfloat16* __restrict__ ol,
                              const float* __restrict__ g, const float* __restrict__ b,
                              const float* __restrict__ g2, const float* __restrict__ b2)
{
    __shared__ float redA[8], redB[8];
    __shared__ float s_m1, s_r1, s_m2, s_r2;
    const int row = blockIdx.x;
    const float4* ip = (const float4*)(in + (size_t)row * HH);
    const float4* pp = (const float4*)(p2 + (size_t)row * HH);
    float4 v0 = ip[threadIdx.x], v1 = ip[threadIdx.x + 256];
    float4 w0 = pp[threadIdx.x], w1 = pp[threadIdx.x + 256];

    float sa = v0.x+v0.y+v0.z+v0.w + v1.x+v1.y+v1.z+v1.w;
    float sb = w0.x+w0.y+w0.z+w0.w + w1.x+w1.y+w1.z+w1.w;
#pragma unroll
    for (int o = 16; o; o >>= 1) {
        sa += __shfl_xor_sync(0xffffffffu, sa, o);
        sb += __shfl_xor_sync(0xffffffffu, sb, o);
    }
    const int wid = threadIdx.x >> 5, lane = threadIdx.x & 31;
    if (lane == 0) { redA[wid] = sa; redB[wid] = sb; }
    __syncthreads();
    if (threadIdx.x == 0) {
        float ta = 0.f, tb2 = 0.f;
#pragma unroll
        for (int i = 0; i < 8; i++) { ta += redA[i]; tb2 += redB[i]; }
        s_m1 = ta * (1.0f / HH);
        s_m2 = tb2 * (1.0f / HH);
    }
    __syncthreads();
    const float m1 = s_m1, m2 = s_m2;
    float d, ssa = 0.f, ssb = 0.f;
    d=v0.x-m1; ssa+=d*d; d=v0.y-m1; ssa+=d*d; d=v0.z-m1; ssa+=d*d; d=v0.w-m1; ssa+=d*d;
    d=v1.x-m1; ssa+=d*d; d=v1.y-m1; ssa+=d*d; d=v1.z-m1; ssa+=d*d; d=v1.w-m1; ssa+=d*d;
    d=w0.x-m2; ssb+=d*d; d=w0.y-m2; ssb+=d*d; d=w0.z-m2; ssb+=d*d; d=w0.w-m2; ssb+=d*d;
    d=w1.x-m2; ssb+=d*d; d=w1.y-m2; ssb+=d*d; d=w1.z-m2; ssb+=d*d; d=w1.w-m2; ssb+=d*d;
#pragma unroll
    for (int o = 16; o; o >>= 1) {
        ssa += __shfl_xor_sync(0xffffffffu, ssa, o);
        ssb += __shfl_xor_sync(0xffffffffu, ssb, o);
    }
    if (lane == 0) { redA[wid] = ssa; redB[wid] = ssb; }
    __syncthreads();
    if (threadIdx.x == 0) {
        float ta = 0.f, tb2 = 0.f;
#pragma unroll
        for (int i = 0; i < 8; i++) { ta += redA[i]; tb2 += redB[i]; }
        s_r1 = rsqrtf(ta * (1.0f / HH) + EPSLN);
        s_r2 = rsqrtf(tb2 * (1.0f / HH) + EPSLN);
    }
    __syncthreads();
    const float r1 = s_r1, r2 = s_r2;

    float4 ga0 = ((const float4*)g)[threadIdx.x],  ga1 = ((const float4*)g)[threadIdx.x + 256];
    float4 ba0 = ((const float4*)b)[threadIdx.x],  ba1 = ((const float4*)b)[threadIdx.x + 256];
    float4 gb0 = ((const float4*)g2)[threadIdx.x], gb1 = ((const float4*)g2)[threadIdx.x + 256];
    float4 bb0 = ((const float4*)b2)[threadIdx.x], bb1 = ((const float4*)b2)[threadIdx.x + 256];

    float4 o0, o1, u0, u1;
    o0.x=(v0.x-m1)*r1*ga0.x+ba0.x; o0.y=(v0.y-m1)*r1*ga0.y+ba0.y;
    o0.z=(v0.z-m1)*r1*ga0.z+ba0.z; o0.w=(v0.w-m1)*r1*ga0.w+ba0.w;
    o1.x=(v1.x-m1)*r1*ga1.x+ba1.x; o1.y=(v1.y-m1)*r1*ga1.y+ba1.y;
    o1.z=(v1.z-m1)*r1*ga1.z+ba1.z; o1.w=(v1.w-m1)*r1*ga1.w+ba1.w;
    u0.x=(w0.x-m2)*r2*gb0.x+bb0.x; u0.y=(w0.y-m2)*r2*gb0.y+bb0.y;
    u0.z=(w0.z-m2)*r2*gb0.z+bb0.z; u0.w=(w0.w-m2)*r2*gb0.w+bb0.w;
    u1.x=(w1.x-m2)*r2*gb1.x+bb1.x; u1.y=(w1.y-m2)*r2*gb1.y+bb1.y;
    u1.z=(w1.z-m2)*r2*gb1.z+bb1.z; u1.w=(w1.w-m2)*r2*gb1.w+bb1.w;
    u0 = silu4(u0); u1 = silu4(u1);
    o0.x*=u0.x; o0.y*=u0.y; o0.z*=u0.z; o0.w*=u0.w;
    o1.x*=u1.x; o1.y*=u1.y; o1.z*=u1.z; o1.w*=u1.w;

    uint2 h0, l0, h1, l1;
    split4(o0, h0, l0);
    split4(o1, h1, l1);
    uint2* hp = (uint2*)(oh + (size_t)row * HH);
    uint2* lp = (uint2*)(ol + (size_t)row * HH);
    hp[threadIdx.x] = h0; hp[threadIdx.x + 256] = h1;
    lp[threadIdx.x] = l0; lp[threadIdx.x + 256] = l1;
}

// ------------------------------- minGRU scan ----------------------------------
__device__ __forceinline__ float softplusf(float x) {
    return fmaxf(x, 0.0f) + log1pf(expf(-fabsf(x)));
}
__device__ __forceinline__ float loggf(float x) {
    return (x >= 0.0f) ? logf(x + 0.5f) : -softplusf(-x);
}
__device__ __forceinline__ float laddexp(float a, float b) {
    float m = fmaxf(a, b);
    float d = fminf(a, b) - m;
    return m + log1pf(expf(d));
}

// one softplus per element: -softplus(-k) == k - softplus(k) (bitwise-equal here)
__global__ void scan_a(const float* __restrict__ Kx, const float* __restrict__ Px,
                       float* __restrict__ rend, float* __restrict__ asum)
{
    const int tid = blockIdx.x * 256 + threadIdx.x;
    const int h = tid & (HH - 1);
    const int rest = tid >> 11;
    const int j = rest & (CHUNKS - 1);
    const int b = rest >> CLOG;
    const size_t base = ((size_t)b * SS + (size_t)j * CLEN) * HH + h;
    float A = 0.f, r = -__int_as_float(0x7f800000);
    for (int tt = 0; tt < CLEN; tt++) {
        const float kv = Kx[base + (size_t)tt * HH];
        const float pv = Px[base + (size_t)tt * HH];
        const float sp = softplusf(kv);
        const float lc = -sp;
        const float lv = (kv - sp) + loggf(pv);
        A += lc;
        r = laddexp(r + lc, lv);
    }
    rend[tid] = r;
    asum[tid] = A;
}

__global__ void scan_b(const float* __restrict__ rend, const float* __restrict__ asum,
                       float* __restrict__ lhin)
{
    const int tid = blockIdx.x * 256 + threadIdx.x;
    const int h = tid & (HH - 1);
    const int b = tid >> 11;
    float carry = -0.69314718056f;
#pragma unroll
    for (int j = 0; j < CHUNKS; j++) {
        const int idx = ((b * CHUNKS + j) << 11) + h;
        lhin[idx] = carry;
        carry = laddexp(asum[idx] + carry, rend[idx]);
    }
}

__global__ void scan_c(const float* __restrict__ Kx, const float* __restrict__ Px,
                       const float* __restrict__ lhin, float* __restrict__ out)
{
    const int tid = blockIdx.x * 256 + threadIdx.x;
    const int h = tid & (HH - 1);
    const int rest = tid >> 11;
    const int j = rest & (CHUNKS - 1);
    const int b = rest >> CLOG;
    const size_t base = ((size_t)b * SS + (size_t)j * CLEN) * HH + h;
    const float lhi = lhin[tid];
    float A = 0.f, r = -__int_as_float(0x7f800000);
    for (int tt = 0; tt < CLEN; tt++) {
        const float kv = Kx[base + (size_t)tt * HH];
        const float pv = Px[base + (size_t)tt * HH];
        const float sp = softplusf(kv);
        const float lc = -sp;
        const float lv = (kv - sp) + loggf(pv);
        A += lc;
        r = laddexp(r + lc, lv);
        out[base + (size_t)tt * HH] = expf(laddexp(r, A + lhi));
    }
}

// --------------------------------- driver -------------------------------------
extern "C" void kernel_launch(void* const* d_in, const int* in_sizes, int n_in,
                              void* d_out, int out_size)
{
    const float* x    = (const float*)d_in[0];
    const float* Wp1  = (const float*)d_in[1];
    const float* bp1  = (const float*)d_in[2];
    const float* Wp2  = (const float*)d_in[3];
    const float* bp2  = (const float*)d_in[4];
    const float* convW= (const float*)d_in[5];
    const float* convb= (const float*)d_in[6];
    const float* Wz   = (const float*)d_in[7];
    const float* bz   = (const float*)d_in[8];
    const float* Wh   = (const float*)d_in[9];
    const float* bh   = (const float*)d_in[10];
    const float* Wd   = (const float*)d_in[11];
    const float* bd   = (const float*)d_in[12];
    const float* lng  = (const float*)d_in[13];
    const float* lnb  = (const float*)d_in[14];
    float* xb = (float*)d_out;

    float *b0,*b2,*b3,*b4,*rend,*asum,*lhin;
    __nv_bfloat16 *cvth,*cvtl,*cvtxh,*cvtxl;
    __nv_bfloat16 *wp1h,*wp1l,*wp2h,*wp2l,*wzh,*wzl,*whh,*whl,*wdh,*wdl,*wch,*wcl;
    cudaGetSymbolAddress((void**)&b0,  g_b0);
    cudaGetSymbolAddress((void**)&b2,  g_b2);
    cudaGetSymbolAddress((void**)&b3,  g_b3);
    cudaGetSymbolAddress((void**)&b4,  g_b4);
    cudaGetSymbolAddress((void**)&rend,g_rend);
    cudaGetSymbolAddress((void**)&asum,g_asum);
    cudaGetSymbolAddress((void**)&lhin,g_lhin);
    cudaGetSymbolAddress((void**)&cvth,g_cvth);
    cudaGetSymbolAddress((void**)&cvtl,g_cvtl);
    cudaGetSymbolAddress((void**)&cvtxh,g_cvtxh);
    cudaGetSymbolAddress((void**)&cvtxl,g_cvtxl);
    cudaGetSymbolAddress((void**)&wp1h,g_wp1h);
    cudaGetSymbolAddress((void**)&wp1l,g_wp1l);
    cudaGetSymbolAddress((void**)&wp2h,g_wp2h);
    cudaGetSymbolAddress((void**)&wp2l,g_wp2l);
    cudaGetSymbolAddress((void**)&wzh, g_wzh);
    cudaGetSymbolAddress((void**)&wzl, g_wzl);
    cudaGetSymbolAddress((void**)&whh, g_whh);
    cudaGetSymbolAddress((void**)&whl, g_whl);
    cudaGetSymbolAddress((void**)&wdh, g_wdh);
    cudaGetSymbolAddress((void**)&wdl, g_wdl);
    cudaGetSymbolAddress((void**)&wch, g_wch);
    cudaGetSymbolAddress((void**)&wcl, g_wcl);

    cudaFuncSetAttribute(gemm_ts, cudaFuncAttributeMaxDynamicSharedMemorySize, SMEM_DYN);

    cudaMemcpyAsync(xb, x, (size_t)MTOK * DD * sizeof(float),
                    cudaMemcpyDeviceToDevice, 0);

    const int npd = LAYERS*HH*DD/4;
    const int nhh = LAYERS*HH*HH/4;
    const dim3 gH(HH/TN, MTOK/TM/2);   // (8, 16) persistent: 2 M-tiles per CTA
    const dim3 gD(DD/TN, MTOK/TM);     // (4, 32) single-tile (128 CTAs, sub-wave)

    // R14-proven launch ordering.
    cvt_split<<<(MTOK*DD/4+255)/256, 256>>>(xb, cvtxh, cvtxl, MTOK*DD/4);
    cvt_split<<<(npd+255)/256, 256>>>(Wp2, wp2h, wp2l, npd);
    cvt_split<<<(npd+255)/256, 256>>>(Wp1, wp1h, wp1l, npd);
    cvt_split<<<(nhh+255)/256, 256>>>(Wz,  wzh,  wzl,  nhh);
    // layer-0 projections hoisted here
    gemm_ts<<<gH, 256, SMEM_DYN>>>(cvtxh, cvtxl, wp2h, wp2l, bp2, b4, HH, DD, 1, 0, 0, 0, 0, 2);
    gemm_ts<<<gH, 256, SMEM_DYN>>>(cvtxh, cvtxl, wp1h, wp1l, bp1, b0, HH, DD, 1, 0, 0, 0, 0, 2);
    // remaining weight conversions
    cvt_split<<<(nhh+255)/256, 256>>>(Wh,  whh,  whl,  nhh);
    cvt_split<<<(npd+255)/256, 256>>>(Wd,  wdh,  wdl,  npd);
    cvt_convw<<<(unsigned)(((size_t)LAYERS*HH*HH+255)/256), 256>>>(convW, wch, wcl);

    for (int i = 0; i < LAYERS; i++) {
        if (i) {
            gemm_ts<<<gH, 256, SMEM_DYN>>>(cvtxh, cvtxl,
                                           wp2h + (size_t)i*HH*DD, wp2l + (size_t)i*HH*DD,
                                           bp2 + i*HH, b4, HH, DD, 1, 0, 0, 0, 0, 2);
            gemm_ts<<<gH, 256, SMEM_DYN>>>(cvtxh, cvtxl,
                                           wp1h + (size_t)i*HH*DD, wp1l + (size_t)i*HH*DD,
                                           bp1 + i*HH, b0, HH, DD, 1, 0, 0, 0, 0, 2);
        }
        ln_split<0><<<MTOK, 256>>>(b0, cvth, cvtl,
                                   lng + (size_t)(i*4+0)*HH, lnb + (size_t)(i*4+0)*HH);

        // conv1d: 3 shifted taps accumulated in TMEM; LN1+SiLU -> split
        gemm_ts<<<gH, 256, SMEM_DYN>>>(cvth, cvtl,
                                       wch + (size_t)i*3*HH*HH, wcl + (size_t)i*3*HH*HH,
                                       convb + i*HH, b0, HH, HH, 3, (size_t)HH*HH, 0, 0, 0, 2);
        ln_split<1><<<MTOK, 256>>>(b0, cvth, cvtl,
                                   lng + (size_t)(i*4+1)*HH, lnb + (size_t)(i*4+1)*HH);

        // minGRU projections + scan
        gemm_ts<<<gH, 256, SMEM_DYN>>>(cvth, cvtl,
                                       wzh + (size_t)i*HH*HH, wzl + (size_t)i*HH*HH,
                                       bz + i*HH, b2, HH, HH, 1, 0, 0, 0, 0, 2);
        gemm_ts<<<gH, 256, SMEM_DYN>>>(cvth, cvtl,
                                       whh + (size_t)i*HH*HH, whl + (size_t)i*HH*HH,
                                       bh + i*HH, b3, HH, HH, 1, 0, 0, 0, 0, 2);
        scan_a<<<(BB*CHUNKS*HH)/256, 256>>>(b2, b3, rend, asum);
        scan_b<<<(BB*HH)/256, 256>>>(rend, asum, lhin);
        scan_c<<<(BB*CHUNKS*HH)/256, 256>>>(b2, b3, lhin, b0);

        // gating: split( LN2(scan_out) * SiLU(LN3(proj2_raw)) )  — fused double-LN
        ln2_mul_split<<<MTOK, 256>>>(b0, b4, cvth, cvtl,
                                     lng + (size_t)(i*4+2)*HH, lnb + (size_t)(i*4+2)*HH,
                                     lng + (size_t)(i*4+3)*HH, lnb + (size_t)(i*4+3)*HH);

        // down projection + bias + residual; epilogue also emits next layer's x split
        gemm_ts<<<gD, 256, SMEM_DYN>>>(cvth, cvtl,
                                       wdh + (size_t)i*DD*HH, wdl + (size_t)i*DD*HH,
                                       bd + i*DD, xb, DD, HH, 1, 0, 1, cvtxh, cvtxl, 1);
    }
}